// round 10
// baseline (speedup 1.0000x reference)
#include <cuda_runtime.h>
#include <math.h>

#define BB 4
#define NN 2000
#define CCLS 80
#define KTOP 2000
#define CAP 8192
#define CMAX 160
#define SCORE_THR 0.05f
#define IOU_THR 0.5f
#define MAXR 4.135166556742356f   /* |log(16/1000)| */

#define NB 5120                    /* buckets: 5 per thread @ 1024 threads */
#define SCAP 4096
#define BUCKET_BASE 125542u        /* 0x3D4CCCCD >> 13  (0.05f) */

#define NBLK_SC 63                 /* ceil(2000/32) score blocks per image */

// ---------------- device scratch (zero at load; reset in-kernel each call) ----------------
__device__ unsigned long long g_keys[BB][CAP];
__device__ int g_count[BB];
__device__ int g_done[BB];
__device__ int g_done2[BB];
__device__ unsigned long long g_skey[BB][KTOP];
__device__ unsigned char g_slab[BB][KTOP];
__device__ float4 g_boxv[BB][KTOP];
__device__ unsigned char g_keep[BB][KTOP];

// ================= K1: softmax/threshold/compact + (last block per image) bucket sort =================
// smem: [0,20480) hist(int[5120]) UNION score-buf(u64[2560]);  [20480,53248) ssort u64[4096]
#define K1_TOTAL 53248

__global__ void __launch_bounds__(1024, 2) k_score_sort(const float* __restrict__ cls) {
    extern __shared__ unsigned char smem[];
    int* hist = (int*)smem;
    unsigned long long* buf = (unsigned long long*)smem;       // union with hist
    unsigned long long* ssort = (unsigned long long*)(smem + 20480);
    __shared__ int bcnt, gbase, isLast;
    __shared__ int wtot[32];

    int b = blockIdx.y;
    int tid = threadIdx.x;
    int wid = tid >> 5, lane = tid & 31;
    int n = blockIdx.x * 32 + wid;

    if (tid == 0) bcnt = 0;
    __syncthreads();

    // ---- score phase: one warp per proposal ----
    if (n < NN) {
        const float* p = cls + ((size_t)b * NN + n) * (CCLS + 1);
        float x0 = p[lane];
        float x1 = p[lane + 32];
        float x2 = (lane < 17) ? p[lane + 64] : -1e30f;   // idx 80 = background
        float m = fmaxf(x0, fmaxf(x1, x2));
        #pragma unroll
        for (int o = 16; o > 0; o >>= 1) m = fmaxf(m, __shfl_xor_sync(0xffffffffu, m, o));
        float e0 = expf(x0 - m);
        float e1 = expf(x1 - m);
        float e2 = (lane < 17) ? expf(x2 - m) : 0.f;
        float s = e0 + e1 + e2;
        #pragma unroll
        for (int o = 16; o > 0; o >>= 1) s += __shfl_xor_sync(0xffffffffu, s, o);

        float sc;
        sc = e0 / s;
        if (sc > SCORE_THR) {
            unsigned idx = (unsigned)(n * CCLS + lane);
            buf[atomicAdd(&bcnt, 1)] = ((unsigned long long)__float_as_uint(sc) << 32) | (0xFFFFFFFFu - idx);
        }
        sc = e1 / s;
        if (sc > SCORE_THR) {
            unsigned idx = (unsigned)(n * CCLS + lane + 32);
            buf[atomicAdd(&bcnt, 1)] = ((unsigned long long)__float_as_uint(sc) << 32) | (0xFFFFFFFFu - idx);
        }
        if (lane < 16) {
            sc = e2 / s;
            if (sc > SCORE_THR) {
                unsigned idx = (unsigned)(n * CCLS + lane + 64);
                buf[atomicAdd(&bcnt, 1)] = ((unsigned long long)__float_as_uint(sc) << 32) | (0xFFFFFFFFu - idx);
            }
        }
    }
    __syncthreads();
    if (tid == 0) gbase = atomicAdd(&g_count[b], bcnt);
    __syncthreads();
    {
        int nb = bcnt, gb = gbase;
        for (int i = tid; i < nb; i += 1024) {
            int pos = gb + i;
            if (pos < CAP) g_keys[b][pos] = buf[i];
        }
    }
    __threadfence();
    if (tid == 0) {
        int old = atomicAdd(&g_done[b], 1);
        isLast = (old == NBLK_SC - 1);
    }
    __syncthreads();
    if (!isLast) return;
    __threadfence();

    // ---- sort phase (this image's last-arriving block; full 1024 threads) ----
    int cnt = min(g_count[b], CAP);

    for (int i = tid; i < NB; i += 1024) hist[i] = 0;
    for (int i = tid; i < SCAP; i += 1024) ssort[i] = 0ull;
    __syncthreads();

    // cache keys in registers (single global read), histogram
    unsigned long long kreg[8];
    int nk = 0;
    for (int i = tid; i < cnt; i += 1024) {
        unsigned long long key = g_keys[b][i];
        kreg[nk++] = key;
        unsigned u = (unsigned)(key >> 32);
        int bkt = min(max((int)((u >> 13) - BUCKET_BASE), 0), NB - 1);
        atomicAdd(&hist[bkt], 1);
    }
    __syncthreads();

    // suffix exclusive scan: start[bkt] = #items in higher buckets
    int lc[5];
    int lsum = 0;
    #pragma unroll
    for (int k = 0; k < 5; k++) {
        lc[k] = hist[NB - 1 - (tid * 5 + k)];
        lsum += lc[k];
    }
    int incl = lsum;
    #pragma unroll
    for (int o = 1; o < 32; o <<= 1) {
        int v = __shfl_up_sync(0xffffffffu, incl, o);
        if (lane >= o) incl += v;
    }
    if (lane == 31) wtot[wid] = incl;
    __syncthreads();
    if (wid == 0) {
        int v = wtot[lane];
        int i2 = v;
        #pragma unroll
        for (int o = 1; o < 32; o <<= 1) {
            int u2 = __shfl_up_sync(0xffffffffu, i2, o);
            if (lane >= o) i2 += u2;
        }
        wtot[lane] = i2 - v;
    }
    __syncthreads();
    int run = wtot[wid] + incl - lsum;
    #pragma unroll
    for (int k = 0; k < 5; k++) {
        int bkt = NB - 1 - (tid * 5 + k);
        int c = lc[k];
        hist[bkt] = run;
        run += c;
    }
    __syncthreads();

    // scatter from registers
    for (int q = 0; q < nk; q++) {
        unsigned long long key = kreg[q];
        unsigned u = (unsigned)(key >> 32);
        int bkt = min(max((int)((u >> 13) - BUCKET_BASE), 0), NB - 1);
        int pos = atomicAdd(&hist[bkt], 1);
        if (pos < SCAP) ssort[pos] = key;
    }
    __syncthreads();

    // per-bucket insertion fix-up (full 64-bit key = unique total order -> deterministic)
    for (int bkt = tid; bkt < NB; bkt += 1024) {
        int e0 = hist[bkt];
        int s0 = (bkt == NB - 1) ? 0 : hist[bkt + 1];
        if (s0 >= KTOP) continue;
        if (e0 > SCAP) e0 = SCAP;
        for (int i = s0 + 1; i < e0; i++) {
            unsigned long long v = ssort[i];
            int j = i - 1;
            while (j >= s0 && ssort[j] < v) { ssort[j + 1] = ssort[j]; j--; }
            ssort[j + 1] = v;
        }
    }
    __syncthreads();

    for (int s = tid; s < KTOP; s += 1024) {
        unsigned long long key = ssort[s];
        g_skey[b][s] = key;
        unsigned char l = 255;
        if (s < cnt && key != 0ull) {
            unsigned idx = 0xFFFFFFFFu - (unsigned)(key & 0xFFFFFFFFu);
            l = (unsigned char)(idx % CCLS);
        }
        g_slab[b][s] = l;
    }
    if (tid == 0) { g_count[b] = 0; g_done[b] = 0; }   // invariant state for next replay
}

// ================= K2: per-class NMS + (last block per image) top-100 output =================
__global__ void k_nms_out(const float* __restrict__ reg, const float* __restrict__ props,
                          const int* __restrict__ hw, float* __restrict__ out) {
    __shared__ unsigned char slab[2048];
    __shared__ unsigned char skeep[2048];
    __shared__ unsigned short list[CMAX];
    __shared__ float4 bx[CMAX];
    __shared__ float ar[CMAX];
    __shared__ unsigned char sup[CMAX];
    __shared__ int wsum[8];
    __shared__ int scnt, isLast;

    int c = blockIdx.x, b = blockIdx.y;
    int tid = threadIdx.x;
    int wid = tid >> 5, lane = tid & 31;

    float h = (float)hw[b * 2 + 0], w = (float)hw[b * 2 + 1];
    float offs = fmaxf(h, w) + 1.0f;

    // coalesced label load (2000 bytes)
    {
        const uint4* src = (const uint4*)g_slab[b];
        if (tid < 125) ((uint4*)slab)[tid] = src[tid];
        if (tid < 48) slab[2000 + tid] = 255;
    }
    __syncthreads();

    // stable compaction: thread t owns s in [t*8, t*8+8)
    int f[8], pf = 0;
    #pragma unroll
    for (int i = 0; i < 8; i++) {
        int s = tid * 8 + i;
        f[i] = (s < KTOP) && (slab[s] == (unsigned char)c);
        pf += f[i];
    }
    int incl = pf;
    #pragma unroll
    for (int o = 1; o < 32; o <<= 1) {
        int v = __shfl_up_sync(0xffffffffu, incl, o);
        if (lane >= o) incl += v;
    }
    if (lane == 31) wsum[wid] = incl;
    __syncthreads();
    if (tid < 8) {
        int v = wsum[tid];
        int i2 = v;
        #pragma unroll
        for (int o = 1; o < 8; o <<= 1) {
            int u2 = __shfl_up_sync(0xffu, i2, o);
            if (tid >= o) i2 += u2;
        }
        wsum[tid] = i2 - v;
        if (tid == 7) scnt = i2;
    }
    __syncthreads();
    int r = wsum[wid] + incl - pf;
    #pragma unroll
    for (int i = 0; i < 8; i++) {
        if (f[i]) {
            int s = tid * 8 + i;
            if (r < CMAX) list[r] = (unsigned short)s;
            else g_keep[b][s] = 0;           // overflow: drop deterministically
            r++;
        }
    }
    __syncthreads();

    int k = min(scnt, CMAX);
    if (k > 0) {
        float off = (float)c * offs;
        // decode this class's boxes (with class offset; matches reference fp rounding)
        for (int i = tid; i < k; i += 256) {
            int s = list[i];
            unsigned long long key = g_skey[b][s];
            unsigned idx = 0xFFFFFFFFu - (unsigned)(key & 0xFFFFFFFFu);
            int n = idx / CCLS;
            const float* pb = props + ((size_t)b * NN + n) * 4;
            const float* d = reg + (((size_t)b * NN + n) * CCLS + c) * 4;
            float dx = d[0] * 0.1f, dy = d[1] * 0.1f;
            float dw = fminf(fmaxf(d[2] * 0.2f, -MAXR), MAXR);
            float dh = fminf(fmaxf(d[3] * 0.2f, -MAXR), MAXR);
            float px = (pb[0] + pb[2]) * 0.5f, py = (pb[1] + pb[3]) * 0.5f;
            float pw = pb[2] - pb[0], ph = pb[3] - pb[1];
            float gx = px + pw * dx, gy = py + ph * dy;
            float gw = pw * expf(dw), gh = ph * expf(dh);
            float x1 = fminf(fmaxf(gx - gw * 0.5f, 0.f), w) + off;
            float y1 = fminf(fmaxf(gy - gh * 0.5f, 0.f), h) + off;
            float x2 = fminf(fmaxf(gx + gw * 0.5f, 0.f), w) + off;
            float y2 = fminf(fmaxf(gy + gh * 0.5f, 0.f), h) + off;
            float4 B = make_float4(x1, y1, x2, y2);
            bx[i] = B;
            ar[i] = (x2 - x1) * (y2 - y1);
            sup[i] = 0;
            g_boxv[b][s] = B;
        }
        __syncthreads();

        // greedy NMS (warp 0); list is in descending score order
        if (wid == 0) {
            for (int a = 0; a < k - 1; a++) {
                if (!sup[a]) {
                    float4 A = bx[a];
                    float aa = ar[a];
                    for (int t = a + 1 + lane; t < k; t += 32) {
                        if (sup[t]) continue;
                        float4 Bx = bx[t];
                        float ix1 = fmaxf(A.x, Bx.x);
                        float iy1 = fmaxf(A.y, Bx.y);
                        float ix2 = fminf(A.z, Bx.z);
                        float iy2 = fminf(A.w, Bx.w);
                        float iw = fmaxf(ix2 - ix1, 0.f), ih = fmaxf(iy2 - iy1, 0.f);
                        float inter = iw * ih;
                        float iou = inter / (aa + ar[t] - inter + 1e-6f);
                        if (iou > IOU_THR) sup[t] = 1;
                    }
                }
                __syncwarp();
            }
        }
        __syncthreads();

        for (int i = tid; i < k; i += 256) g_keep[b][list[i]] = 1 - sup[i];
    }

    // ---- arrive; last class block for this image writes the output ----
    __threadfence();
    if (tid == 0) {
        int old = atomicAdd(&g_done2[b], 1);
        isLast = (old == CCLS - 1);
    }
    __syncthreads();
    if (!isLast) return;
    __threadfence();

    // reload keep flags (slab already resident in smem)
    {
        const uint4* s2 = (const uint4*)g_keep[b];
        if (tid < 125) ((uint4*)skeep)[tid] = s2[tid];
    }
    float* ob = out;
    float* os = out + BB * 100 * 4;
    float* ol = out + BB * 100 * 5;
    for (int rr = tid; rr < 100; rr += 256) {
        ob[(b * 100 + rr) * 4 + 0] = 0.f;
        ob[(b * 100 + rr) * 4 + 1] = 0.f;
        ob[(b * 100 + rr) * 4 + 2] = 0.f;
        ob[(b * 100 + rr) * 4 + 3] = 0.f;
        os[b * 100 + rr] = 0.f;
        ol[b * 100 + rr] = -1.f;
    }
    __syncthreads();

    // rank scan of keep flags (8 per thread) and top-100 write
    int kf[8], pk = 0;
    #pragma unroll
    for (int i = 0; i < 8; i++) {
        int s = tid * 8 + i;
        kf[i] = (s < KTOP) && (slab[s] != 255) && skeep[s];
        pk += kf[i];
    }
    int inc2 = pk;
    #pragma unroll
    for (int o = 1; o < 32; o <<= 1) {
        int v = __shfl_up_sync(0xffffffffu, inc2, o);
        if (lane >= o) inc2 += v;
    }
    if (lane == 31) wsum[wid] = inc2;
    __syncthreads();
    if (tid < 8) {
        int v = wsum[tid];
        int i3 = v;
        #pragma unroll
        for (int o = 1; o < 8; o <<= 1) {
            int u3 = __shfl_up_sync(0xffu, i3, o);
            if (tid >= o) i3 += u3;
        }
        wsum[tid] = i3 - v;
    }
    __syncthreads();
    int rank = wsum[wid] + inc2 - pk;
    #pragma unroll
    for (int i = 0; i < 8; i++) {
        if (kf[i]) {
            if (rank < 100) {
                int s = tid * 8 + i;
                float off = (float)slab[s] * offs;
                float4 B = g_boxv[b][s];
                ob[(b * 100 + rank) * 4 + 0] = B.x - off;
                ob[(b * 100 + rank) * 4 + 1] = B.y - off;
                ob[(b * 100 + rank) * 4 + 2] = B.z - off;
                ob[(b * 100 + rank) * 4 + 3] = B.w - off;
                os[b * 100 + rank] = __uint_as_float((unsigned)(g_skey[b][s] >> 32));
                ol[b * 100 + rank] = (float)slab[s];
            }
            rank++;
        }
    }
    if (tid == 0) g_done2[b] = 0;   // invariant state for next replay
}

// ---------------- launch ----------------
extern "C" void kernel_launch(void* const* d_in, const int* in_sizes, int n_in,
                              void* d_out, int out_size) {
    const float* cls   = (const float*)d_in[0];   // [B,N,81]
    const float* reg   = (const float*)d_in[1];   // [B,N,320]
    const float* props = (const float*)d_in[2];   // [B,N,4]
    const int*   hw    = (const int*)d_in[3];     // [B,2]
    float* out = (float*)d_out;

    cudaFuncSetAttribute(k_score_sort, cudaFuncAttributeMaxDynamicSharedMemorySize, K1_TOTAL);

    k_score_sort<<<dim3(NBLK_SC, BB), 1024, K1_TOTAL>>>(cls);
    k_nms_out<<<dim3(CCLS, BB), 256>>>(reg, props, hw, out);
}

// round 12
// speedup vs baseline: 1.4604x; 1.4604x over previous
#include <cuda_runtime.h>
#include <math.h>

#define BB 4
#define NN 2000
#define CCLS 80
#define KTOP 2000
#define CAP 8192
#define CMAX 160
#define SCORE_THR 0.05f
#define IOU_THR 0.5f
#define MAXR 4.135166556742356f   /* |log(16/1000)| */

#define NB 5120                    /* buckets: 5 per thread @ 1024 threads */
#define SCAP 4096
#define BUCKET_BASE 125542u        /* 0x3D4CCCCD >> 13  (0.05f) */

#define NBLK_SC 63                 /* ceil(2000/32) score blocks per image */

// ---------------- device scratch (zero at load; reset in-kernel each call) ----------------
__device__ unsigned long long g_keys[BB][CAP];
__device__ int g_count[BB];
__device__ int g_done[BB];
__device__ int g_done2[BB];
__device__ unsigned long long g_skey[BB][KTOP];
__device__ unsigned char g_slab[BB][KTOP];
__device__ float4 g_boxv[BB][KTOP];
__device__ unsigned char g_keep[BB][KTOP];

// ================= K1: softmax/threshold/compact + (last block per image) bucket sort =================
// smem: [0,20480) hist(int[5120]) UNION score-buf(u64[2560]);  [20480,53248) ssort u64[4096]
#define K1_TOTAL 53248

__global__ void __launch_bounds__(1024, 2) k_score_sort(const float* __restrict__ cls) {
    extern __shared__ unsigned char smem[];
    int* hist = (int*)smem;
    unsigned long long* buf = (unsigned long long*)smem;       // union with hist
    unsigned long long* ssort = (unsigned long long*)(smem + 20480);
    __shared__ int bcnt, gbase, isLast;
    __shared__ int wtot[32];

    int b = blockIdx.y;
    int tid = threadIdx.x;
    int wid = tid >> 5, lane = tid & 31;
    int n = blockIdx.x * 32 + wid;

    if (tid == 0) bcnt = 0;
    __syncthreads();

    // ---- score phase: one warp per proposal ----
    if (n < NN) {
        const float* p = cls + ((size_t)b * NN + n) * (CCLS + 1);
        float x0 = p[lane];
        float x1 = p[lane + 32];
        float x2 = (lane < 17) ? p[lane + 64] : -1e30f;   // idx 80 = background
        float m = fmaxf(x0, fmaxf(x1, x2));
        #pragma unroll
        for (int o = 16; o > 0; o >>= 1) m = fmaxf(m, __shfl_xor_sync(0xffffffffu, m, o));
        float e0 = expf(x0 - m);
        float e1 = expf(x1 - m);
        float e2 = (lane < 17) ? expf(x2 - m) : 0.f;
        float s = e0 + e1 + e2;
        #pragma unroll
        for (int o = 16; o > 0; o >>= 1) s += __shfl_xor_sync(0xffffffffu, s, o);

        float sc;
        sc = e0 / s;
        if (sc > SCORE_THR) {
            unsigned idx = (unsigned)(n * CCLS + lane);
            buf[atomicAdd(&bcnt, 1)] = ((unsigned long long)__float_as_uint(sc) << 32) | (0xFFFFFFFFu - idx);
        }
        sc = e1 / s;
        if (sc > SCORE_THR) {
            unsigned idx = (unsigned)(n * CCLS + lane + 32);
            buf[atomicAdd(&bcnt, 1)] = ((unsigned long long)__float_as_uint(sc) << 32) | (0xFFFFFFFFu - idx);
        }
        if (lane < 16) {
            sc = e2 / s;
            if (sc > SCORE_THR) {
                unsigned idx = (unsigned)(n * CCLS + lane + 64);
                buf[atomicAdd(&bcnt, 1)] = ((unsigned long long)__float_as_uint(sc) << 32) | (0xFFFFFFFFu - idx);
            }
        }
    }
    __syncthreads();
    if (tid == 0) gbase = atomicAdd(&g_count[b], bcnt);
    __syncthreads();
    {
        int nb = bcnt, gb = gbase;
        for (int i = tid; i < nb; i += 1024) {
            int pos = gb + i;
            if (pos < CAP) g_keys[b][pos] = buf[i];
        }
    }
    // ---- release + election: fence by ONE thread only (documented last-block pattern) ----
    __syncthreads();
    if (tid == 0) {
        __threadfence();
        int old = atomicAdd(&g_done[b], 1);
        isLast = (old == NBLK_SC - 1);
        if (isLast) __threadfence();    // acquire side
    }
    __syncthreads();
    if (!isLast) return;

    // ---- sort phase (this image's last-arriving block; full 1024 threads) ----
    int cnt = min(g_count[b], CAP);

    for (int i = tid; i < NB; i += 1024) hist[i] = 0;
    for (int i = tid; i < SCAP; i += 1024) ssort[i] = 0ull;
    __syncthreads();

    // cache keys in registers (single global read, L2-only), histogram
    unsigned long long kreg[8];
    int nk = 0;
    for (int i = tid; i < cnt; i += 1024) {
        unsigned long long key = __ldcg(&g_keys[b][i]);
        kreg[nk++] = key;
        unsigned u = (unsigned)(key >> 32);
        int bkt = min(max((int)((u >> 13) - BUCKET_BASE), 0), NB - 1);
        atomicAdd(&hist[bkt], 1);
    }
    __syncthreads();

    // suffix exclusive scan: start[bkt] = #items in higher buckets
    int lc[5];
    int lsum = 0;
    #pragma unroll
    for (int k = 0; k < 5; k++) {
        lc[k] = hist[NB - 1 - (tid * 5 + k)];
        lsum += lc[k];
    }
    int incl = lsum;
    #pragma unroll
    for (int o = 1; o < 32; o <<= 1) {
        int v = __shfl_up_sync(0xffffffffu, incl, o);
        if (lane >= o) incl += v;
    }
    if (lane == 31) wtot[wid] = incl;
    __syncthreads();
    if (wid == 0) {
        int v = wtot[lane];
        int i2 = v;
        #pragma unroll
        for (int o = 1; o < 32; o <<= 1) {
            int u2 = __shfl_up_sync(0xffffffffu, i2, o);
            if (lane >= o) i2 += u2;
        }
        wtot[lane] = i2 - v;
    }
    __syncthreads();
    int run = wtot[wid] + incl - lsum;
    #pragma unroll
    for (int k = 0; k < 5; k++) {
        int bkt = NB - 1 - (tid * 5 + k);
        int c = lc[k];
        hist[bkt] = run;
        run += c;
    }
    __syncthreads();

    // scatter from registers
    for (int q = 0; q < nk; q++) {
        unsigned long long key = kreg[q];
        unsigned u = (unsigned)(key >> 32);
        int bkt = min(max((int)((u >> 13) - BUCKET_BASE), 0), NB - 1);
        int pos = atomicAdd(&hist[bkt], 1);
        if (pos < SCAP) ssort[pos] = key;
    }
    __syncthreads();

    // per-bucket insertion fix-up (full 64-bit key = unique total order -> deterministic)
    for (int bkt = tid; bkt < NB; bkt += 1024) {
        int e0 = hist[bkt];
        int s0 = (bkt == NB - 1) ? 0 : hist[bkt + 1];
        if (s0 >= KTOP) continue;
        if (e0 > SCAP) e0 = SCAP;
        for (int i = s0 + 1; i < e0; i++) {
            unsigned long long v = ssort[i];
            int j = i - 1;
            while (j >= s0 && ssort[j] < v) { ssort[j + 1] = ssort[j]; j--; }
            ssort[j + 1] = v;
        }
    }
    __syncthreads();

    for (int s = tid; s < KTOP; s += 1024) {
        unsigned long long key = ssort[s];
        g_skey[b][s] = key;
        unsigned char l = 255;
        if (s < cnt && key != 0ull) {
            unsigned idx = 0xFFFFFFFFu - (unsigned)(key & 0xFFFFFFFFu);
            l = (unsigned char)(idx % CCLS);
        }
        g_slab[b][s] = l;
    }
    if (tid == 0) { g_count[b] = 0; g_done[b] = 0; }   // invariant state for next replay
}

// ================= K2: per-class NMS + (last block per image) top-100 output =================
__global__ void k_nms_out(const float* __restrict__ reg, const float* __restrict__ props,
                          const int* __restrict__ hw, float* __restrict__ out) {
    __shared__ unsigned char slab[2048];
    __shared__ unsigned char skeep[2048];
    __shared__ unsigned short list[CMAX];
    __shared__ float4 bx[CMAX];
    __shared__ float ar[CMAX];
    __shared__ unsigned char sup[CMAX];
    __shared__ int wsum[8];
    __shared__ int scnt, isLast;

    int c = blockIdx.x, b = blockIdx.y;
    int tid = threadIdx.x;
    int wid = tid >> 5, lane = tid & 31;

    float h = (float)hw[b * 2 + 0], w = (float)hw[b * 2 + 1];
    float offs = fmaxf(h, w) + 1.0f;

    // coalesced label load (2000 bytes)
    {
        const uint4* src = (const uint4*)g_slab[b];
        if (tid < 125) ((uint4*)slab)[tid] = src[tid];
        if (tid < 48) slab[2000 + tid] = 255;
    }
    __syncthreads();

    // stable compaction: thread t owns s in [t*8, t*8+8)
    int f[8], pf = 0;
    #pragma unroll
    for (int i = 0; i < 8; i++) {
        int s = tid * 8 + i;
        f[i] = (s < KTOP) && (slab[s] == (unsigned char)c);
        pf += f[i];
    }
    int incl = pf;
    #pragma unroll
    for (int o = 1; o < 32; o <<= 1) {
        int v = __shfl_up_sync(0xffffffffu, incl, o);
        if (lane >= o) incl += v;
    }
    if (lane == 31) wsum[wid] = incl;
    __syncthreads();
    if (tid < 8) {
        int v = wsum[tid];
        int i2 = v;
        #pragma unroll
        for (int o = 1; o < 8; o <<= 1) {
            int u2 = __shfl_up_sync(0xffu, i2, o);
            if (tid >= o) i2 += u2;
        }
        wsum[tid] = i2 - v;
        if (tid == 7) scnt = i2;
    }
    __syncthreads();
    int r = wsum[wid] + incl - pf;
    #pragma unroll
    for (int i = 0; i < 8; i++) {
        if (f[i]) {
            int s = tid * 8 + i;
            if (r < CMAX) list[r] = (unsigned short)s;
            else g_keep[b][s] = 0;           // overflow: drop deterministically
            r++;
        }
    }
    __syncthreads();

    int k = min(scnt, CMAX);
    if (k > 0) {
        float off = (float)c * offs;
        // decode this class's boxes (with class offset; matches reference fp rounding)
        for (int i = tid; i < k; i += 256) {
            int s = list[i];
            unsigned long long key = g_skey[b][s];
            unsigned idx = 0xFFFFFFFFu - (unsigned)(key & 0xFFFFFFFFu);
            int n = idx / CCLS;
            const float* pb = props + ((size_t)b * NN + n) * 4;
            const float* d = reg + (((size_t)b * NN + n) * CCLS + c) * 4;
            float dx = d[0] * 0.1f, dy = d[1] * 0.1f;
            float dw = fminf(fmaxf(d[2] * 0.2f, -MAXR), MAXR);
            float dh = fminf(fmaxf(d[3] * 0.2f, -MAXR), MAXR);
            float px = (pb[0] + pb[2]) * 0.5f, py = (pb[1] + pb[3]) * 0.5f;
            float pw = pb[2] - pb[0], ph = pb[3] - pb[1];
            float gx = px + pw * dx, gy = py + ph * dy;
            float gw = pw * expf(dw), gh = ph * expf(dh);
            float x1 = fminf(fmaxf(gx - gw * 0.5f, 0.f), w) + off;
            float y1 = fminf(fmaxf(gy - gh * 0.5f, 0.f), h) + off;
            float x2 = fminf(fmaxf(gx + gw * 0.5f, 0.f), w) + off;
            float y2 = fminf(fmaxf(gy + gh * 0.5f, 0.f), h) + off;
            float4 B = make_float4(x1, y1, x2, y2);
            bx[i] = B;
            ar[i] = (x2 - x1) * (y2 - y1);
            sup[i] = 0;
            g_boxv[b][s] = B;
        }
        __syncthreads();

        // greedy NMS (warp 0); list is in descending score order
        if (wid == 0) {
            for (int a = 0; a < k - 1; a++) {
                if (!sup[a]) {
                    float4 A = bx[a];
                    float aa = ar[a];
                    for (int t = a + 1 + lane; t < k; t += 32) {
                        if (sup[t]) continue;
                        float4 Bx = bx[t];
                        float ix1 = fmaxf(A.x, Bx.x);
                        float iy1 = fmaxf(A.y, Bx.y);
                        float ix2 = fminf(A.z, Bx.z);
                        float iy2 = fminf(A.w, Bx.w);
                        float iw = fmaxf(ix2 - ix1, 0.f), ih = fmaxf(iy2 - iy1, 0.f);
                        float inter = iw * ih;
                        float iou = inter / (aa + ar[t] - inter + 1e-6f);
                        if (iou > IOU_THR) sup[t] = 1;
                    }
                }
                __syncwarp();
            }
        }
        __syncthreads();

        for (int i = tid; i < k; i += 256) g_keep[b][list[i]] = 1 - sup[i];
    }

    // ---- release + election: fence by ONE thread only ----
    __syncthreads();
    if (tid == 0) {
        __threadfence();
        int old = atomicAdd(&g_done2[b], 1);
        isLast = (old == CCLS - 1);
        if (isLast) __threadfence();    // acquire side
    }
    __syncthreads();
    if (!isLast) return;

    // reload keep flags L2-only (slab already resident in smem)
    {
        const uint4* s2 = (const uint4*)g_keep[b];
        if (tid < 125) ((uint4*)skeep)[tid] = __ldcg(&s2[tid]);
    }
    float* ob = out;
    float* os = out + BB * 100 * 4;
    float* ol = out + BB * 100 * 5;
    for (int rr = tid; rr < 100; rr += 256) {
        ob[(b * 100 + rr) * 4 + 0] = 0.f;
        ob[(b * 100 + rr) * 4 + 1] = 0.f;
        ob[(b * 100 + rr) * 4 + 2] = 0.f;
        ob[(b * 100 + rr) * 4 + 3] = 0.f;
        os[b * 100 + rr] = 0.f;
        ol[b * 100 + rr] = -1.f;
    }
    __syncthreads();

    // rank scan of keep flags (8 per thread) and top-100 write
    int kf[8], pk = 0;
    #pragma unroll
    for (int i = 0; i < 8; i++) {
        int s = tid * 8 + i;
        kf[i] = (s < KTOP) && (slab[s] != 255) && skeep[s];
        pk += kf[i];
    }
    int inc2 = pk;
    #pragma unroll
    for (int o = 1; o < 32; o <<= 1) {
        int v = __shfl_up_sync(0xffffffffu, inc2, o);
        if (lane >= o) inc2 += v;
    }
    if (lane == 31) wsum[wid] = inc2;
    __syncthreads();
    if (tid < 8) {
        int v = wsum[tid];
        int i3 = v;
        #pragma unroll
        for (int o = 1; o < 8; o <<= 1) {
            int u3 = __shfl_up_sync(0xffu, i3, o);
            if (tid >= o) i3 += u3;
        }
        wsum[tid] = i3 - v;
    }
    __syncthreads();
    int rank = wsum[wid] + inc2 - pk;
    #pragma unroll
    for (int i = 0; i < 8; i++) {
        if (kf[i]) {
            if (rank < 100) {
                int s = tid * 8 + i;
                float off = (float)slab[s] * offs;
                float4 B = __ldcg(&g_boxv[b][s]);
                ob[(b * 100 + rank) * 4 + 0] = B.x - off;
                ob[(b * 100 + rank) * 4 + 1] = B.y - off;
                ob[(b * 100 + rank) * 4 + 2] = B.z - off;
                ob[(b * 100 + rank) * 4 + 3] = B.w - off;
                os[b * 100 + rank] = __uint_as_float((unsigned)(g_skey[b][s] >> 32));
                ol[b * 100 + rank] = (float)slab[s];
            }
            rank++;
        }
    }
    if (tid == 0) g_done2[b] = 0;   // invariant state for next replay
}

// ---------------- launch ----------------
extern "C" void kernel_launch(void* const* d_in, const int* in_sizes, int n_in,
                              void* d_out, int out_size) {
    const float* cls   = (const float*)d_in[0];   // [B,N,81]
    const float* reg   = (const float*)d_in[1];   // [B,N,320]
    const float* props = (const float*)d_in[2];   // [B,N,4]
    const int*   hw    = (const int*)d_in[3];     // [B,2]
    float* out = (float*)d_out;

    cudaFuncSetAttribute(k_score_sort, cudaFuncAttributeMaxDynamicSharedMemorySize, K1_TOTAL);

    k_score_sort<<<dim3(NBLK_SC, BB), 1024, K1_TOTAL>>>(cls);
    k_nms_out<<<dim3(CCLS, BB), 256>>>(reg, props, hw, out);
}